// round 6
// baseline (speedup 1.0000x reference)
#include <cuda_runtime.h>
#include <cuda_bf16.h>
#include <math.h>
#include <stdint.h>

// LogMap via matrix polynomial on the tensor pipe (portable mma.sync m16n8k16 bf16).
// log(X) = p(S), S=(X-m I)/h on [1,6.8]; p = deg-8 Chebyshev fit of log.
// Paterson-Stockmeyer, Z=S^3: 4 matmuls/matrix, each = 3 bf16 MMAs (hi/lo split).
// 2 matrices per CTA (128 thr); 2 warps per matrix (32-row slabs).
// Scheduling: MMAs issued in phases of 8 distinct accumulators so the
// same-accumulator reuse distance is 8 (covers HMMA latency); swizzle
// offsets hoisted to thread-constant bases.

#define DEG 8
struct Coeffs { float b[DEG + 1]; float mshift; float invh; };

// per-matrix smem byte offsets (6 buffers of 64 rows x 128B)
#define SH 0
#define SL 8192
#define TH 16384
#define TL 24576
#define ZH 32768
#define ZL 40960
#define MATSTRIDE 49152
#define SMEM_TOTAL (2 * MATSTRIDE)

__device__ __forceinline__ uint32_t smem_u32(const void* p) {
    uint32_t a;
    asm("{ .reg .u64 t; cvta.to.shared.u64 t, %1; cvt.u32.u64 %0, t; }"
        : "=r"(a) : "l"(p));
    return a;
}

// swizzled byte offset of (row r, byte-col cb) in a 64x128B buffer
__device__ __forceinline__ uint32_t swoff(int r, int cb) {
    return (uint32_t)(r * 128 + ((((cb >> 4) ^ (r & 7))) << 4) + (cb & 15));
}

#define LDMX4(d, addr) \
    asm volatile("ldmatrix.sync.aligned.m8n8.x4.shared.b16 {%0,%1,%2,%3}, [%4];" \
        : "=r"((d)[0]), "=r"((d)[1]), "=r"((d)[2]), "=r"((d)[3]) : "r"(addr))

#define LDMX4T(d, addr) \
    asm volatile("ldmatrix.sync.aligned.m8n8.x4.trans.shared.b16 {%0,%1,%2,%3}, [%4];" \
        : "=r"((d)[0]), "=r"((d)[1]), "=r"((d)[2]), "=r"((d)[3]) : "r"(addr))

#define MMA(c, a, b0v, b1v) \
    asm volatile("mma.sync.aligned.m16n8k16.row.col.f32.bf16.bf16.f32 " \
        "{%0,%1,%2,%3}, {%4,%5,%6,%7}, {%8,%9}, {%0,%1,%2,%3};" \
        : "+f"((c)[0]), "+f"((c)[1]), "+f"((c)[2]), "+f"((c)[3]) \
        : "r"((a)[0]), "r"((a)[1]), "r"((a)[2]), "r"((a)[3]), "r"(b0v), "r"(b1v))

__device__ __forceinline__ uint32_t pk(float a, float b) {
    __nv_bfloat162 t = __floats2bfloat162_rn(a, b);
    return *reinterpret_cast<uint32_t*>(&t);
}
__device__ __forceinline__ float2 upk(uint32_t u) {
    __nv_bfloat162 t = *reinterpret_cast<__nv_bfloat162*>(&u);
    return __bfloat1622float2(t);
}
__device__ __forceinline__ float bhi(float v) {
    return __bfloat162float(__float2bfloat16_rn(v));
}

__device__ __forceinline__ void split_store8(const float* v, char* hi, char* lo) {
    float h0 = bhi(v[0]), h1 = bhi(v[1]), h2 = bhi(v[2]), h3 = bhi(v[3]);
    float h4 = bhi(v[4]), h5 = bhi(v[5]), h6 = bhi(v[6]), h7 = bhi(v[7]);
    *(uint4*)hi = make_uint4(pk(v[0], v[1]), pk(v[2], v[3]), pk(v[4], v[5]), pk(v[6], v[7]));
    *(uint4*)lo = make_uint4(pk(v[0]-h0, v[1]-h1), pk(v[2]-h2, v[3]-h3),
                             pk(v[4]-h4, v[5]-h5), pk(v[6]-h6, v[7]-h7));
}

__global__ void __launch_bounds__(128)
logmap_mma_kernel(const float* __restrict__ X, float* __restrict__ out, Coeffs cf)
{
    extern __shared__ char smraw[];
    const int tid = threadIdx.x;
    const int w = tid >> 5;
    const int l = tid & 31;
    const int mloc = w >> 1;              // matrix within CTA (0/1)
    const int h = w & 1;                  // warp-half: rows [32h, 32h+32)
    const int sr = 32 * h;
    const int lq = l >> 2, lr = l & 3;
    const int lmr = l & 15;
    const int lmc16 = (l >> 4) & 1;       // ldmatrix col-group (0/1)
    const int key = lmr & 7;              // thread-constant swizzle XOR key
    char* sm = smraw + mloc * MATSTRIDE;
    const uint32_t sb = smem_u32(sm);
    const size_t mb = ((size_t)blockIdx.x * 2 + mloc) * 4096;

    // hoisted offset tables
    uint32_t colx[4], kb[4], arow[2];
    #pragma unroll
    for (int j = 0; j < 4; j++) colx[j] = (uint32_t)((((2*j + lmc16) ^ key)) << 4);
    #pragma unroll
    for (int kk = 0; kk < 4; kk++) kb[kk] = (uint32_t)((16*kk + lmr) * 128);
    #pragma unroll
    for (int rb = 0; rb < 2; rb++) arow[rb] = (uint32_t)((sr + 16*rb + lmr) * 128);

    // ---- load 1 row/thread, build S = (X - m I)/h, write S hi/lo ----
    {
        const int row = sr + l;
        const float4* xr = (const float4*)(X + mb + (size_t)row * 64);
        float v[64];
        #pragma unroll
        for (int q = 0; q < 16; q++) {
            float4 f = xr[q];
            v[4*q] = f.x; v[4*q+1] = f.y; v[4*q+2] = f.z; v[4*q+3] = f.w;
        }
        #pragma unroll
        for (int i = 0; i < 64; i++) {
            float t = v[i];
            if (i == row) t -= cf.mshift;
            v[i] = t * cf.invh;
        }
        #pragma unroll
        for (int q = 0; q < 8; q++) {
            uint32_t o = swoff(row, 16 * q);
            split_store8(v + 8 * q, sm + SH + o, sm + SL + o);
        }
    }
    __syncthreads();

    float acc[2][8][4];
    uint32_t ah[2][4][4], al[2][4][4];

    auto zacc = [&] {
        #pragma unroll
        for (int rb = 0; rb < 2; rb++)
            #pragma unroll
            for (int n = 0; n < 8; n++)
                #pragma unroll
                for (int q = 0; q < 4; q++) acc[rb][n][q] = 0.f;
    };

    auto ldaS = [&] {
        #pragma unroll
        for (int rb = 0; rb < 2; rb++)
            #pragma unroll
            for (int kk = 0; kk < 4; kk++) {
                uint32_t o = arow[rb] + colx[kk];
                LDMX4(ah[rb][kk], sb + SH + o);
                LDMX4(al[rb][kk], sb + SL + o);
            }
    };

    // A frags <- acc (hi/lo bf16 split)
    auto cvtA = [&] {
        #pragma unroll
        for (int rb = 0; rb < 2; rb++)
            #pragma unroll
            for (int kk = 0; kk < 4; kk++) {
                float c00 = acc[rb][2*kk][0],   c01 = acc[rb][2*kk][1];
                float c02 = acc[rb][2*kk][2],   c03 = acc[rb][2*kk][3];
                float d00 = acc[rb][2*kk+1][0], d01 = acc[rb][2*kk+1][1];
                float d02 = acc[rb][2*kk+1][2], d03 = acc[rb][2*kk+1][3];
                ah[rb][kk][0] = pk(c00, c01); ah[rb][kk][1] = pk(c02, c03);
                ah[rb][kk][2] = pk(d00, d01); ah[rb][kk][3] = pk(d02, d03);
                al[rb][kk][0] = pk(c00 - bhi(c00), c01 - bhi(c01));
                al[rb][kk][1] = pk(c02 - bhi(c02), c03 - bhi(c03));
                al[rb][kk][2] = pk(d00 - bhi(d00), d01 - bhi(d01));
                al[rb][kk][3] = pk(d02 - bhi(d02), d03 - bhi(d03));
            }
    };

    // acc += A(frags) * B(smem hi/lo); phase-ordered: same-acc distance = 8 MMAs
    auto product = [&](uint32_t bhBase, uint32_t blBase) {
        #pragma unroll
        for (int kk = 0; kk < 4; kk++) {
            #pragma unroll
            for (int jp = 0; jp < 2; jp++) {
                uint32_t o0 = kb[kk] + colx[2*jp], o1 = kb[kk] + colx[2*jp+1];
                uint32_t b0[4], b1[4];
                LDMX4T(b0, bhBase + o0);
                LDMX4T(b1, bhBase + o1);
                // phase 1: ah x bh (8 distinct accs)
                MMA(acc[0][4*jp+0], ah[0][kk], b0[0], b0[1]);
                MMA(acc[1][4*jp+0], ah[1][kk], b0[0], b0[1]);
                MMA(acc[0][4*jp+1], ah[0][kk], b0[2], b0[3]);
                MMA(acc[1][4*jp+1], ah[1][kk], b0[2], b0[3]);
                MMA(acc[0][4*jp+2], ah[0][kk], b1[0], b1[1]);
                MMA(acc[1][4*jp+2], ah[1][kk], b1[0], b1[1]);
                MMA(acc[0][4*jp+3], ah[0][kk], b1[2], b1[3]);
                MMA(acc[1][4*jp+3], ah[1][kk], b1[2], b1[3]);
                // phase 2: al x bh (same 8 accs, distance 8)
                MMA(acc[0][4*jp+0], al[0][kk], b0[0], b0[1]);
                MMA(acc[1][4*jp+0], al[1][kk], b0[0], b0[1]);
                MMA(acc[0][4*jp+1], al[0][kk], b0[2], b0[3]);
                MMA(acc[1][4*jp+1], al[1][kk], b0[2], b0[3]);
                MMA(acc[0][4*jp+2], al[0][kk], b1[0], b1[1]);
                MMA(acc[1][4*jp+2], al[1][kk], b1[0], b1[1]);
                MMA(acc[0][4*jp+3], al[0][kk], b1[2], b1[3]);
                MMA(acc[1][4*jp+3], al[1][kk], b1[2], b1[3]);
                // phase 3: ah x bl
                uint32_t c0[4], c1[4];
                LDMX4T(c0, blBase + o0);
                LDMX4T(c1, blBase + o1);
                MMA(acc[0][4*jp+0], ah[0][kk], c0[0], c0[1]);
                MMA(acc[1][4*jp+0], ah[1][kk], c0[0], c0[1]);
                MMA(acc[0][4*jp+1], ah[0][kk], c0[2], c0[3]);
                MMA(acc[1][4*jp+1], ah[1][kk], c0[2], c0[3]);
                MMA(acc[0][4*jp+2], ah[0][kk], c1[0], c1[1]);
                MMA(acc[1][4*jp+2], ah[1][kk], c1[0], c1[1]);
                MMA(acc[0][4*jp+3], ah[0][kk], c1[2], c1[3]);
                MMA(acc[1][4*jp+3], ah[1][kk], c1[2], c1[3]);
            }
        }
    };

    auto stacc = [&](int hB, int lB) {
        #pragma unroll
        for (int rb = 0; rb < 2; rb++) {
            int r0 = sr + 16 * rb + lq, r1 = r0 + 8;
            #pragma unroll
            for (int n = 0; n < 8; n++) {
                int cb = 16 * n + 4 * lr;
                float a0 = acc[rb][n][0], a1 = acc[rb][n][1];
                float a2 = acc[rb][n][2], a3 = acc[rb][n][3];
                *(uint32_t*)(sm + hB + swoff(r0, cb)) = pk(a0, a1);
                *(uint32_t*)(sm + hB + swoff(r1, cb)) = pk(a2, a3);
                *(uint32_t*)(sm + lB + swoff(r0, cb)) = pk(a0 - bhi(a0), a1 - bhi(a1));
                *(uint32_t*)(sm + lB + swoff(r1, cb)) = pk(a2 - bhi(a2), a3 - bhi(a3));
            }
        }
    };

    // acc = b0*I + b1*S + b2*T (overwrites acc)
    auto epi = [&](float b0, float b1, float b2) {
        #pragma unroll
        for (int rb = 0; rb < 2; rb++) {
            #pragma unroll
            for (int g = 0; g < 4; g++) {
                uint32_t shf[4], slf[4], thf[4], tlf[4];
                uint32_t o = arow[rb] + colx[g];
                LDMX4(shf, sb + SH + o);
                LDMX4(slf, sb + SL + o);
                LDMX4(thf, sb + TH + o);
                LDMX4(tlf, sb + TL + o);
                #pragma unroll
                for (int q = 0; q < 4; q++) {
                    float2 s = upk(shf[q]), s2 = upk(slf[q]);
                    float2 t = upk(thf[q]), t2 = upk(tlf[q]);
                    float sx = s.x + s2.x, sy = s.y + s2.y;
                    float tx = t.x + t2.x, ty = t.y + t2.y;
                    int n = 2 * g + (q >> 1), c = (q & 1) * 2;
                    acc[rb][n][c]     = b1 * sx + b2 * tx;
                    acc[rb][n][c + 1] = b1 * sy + b2 * ty;
                }
            }
            int r0 = sr + 16 * rb + lq, r1 = r0 + 8;
            #pragma unroll
            for (int n = 0; n < 8; n++) {
                int c0 = 8 * n + 2 * lr;
                if (c0 == r0)     acc[rb][n][0] += b0;
                if (c0 + 1 == r0) acc[rb][n][1] += b0;
                if (c0 == r1)     acc[rb][n][2] += b0;
                if (c0 + 1 == r1) acc[rb][n][3] += b0;
            }
        }
    };

    // ---- T = S*S ----
    ldaS();
    zacc();
    product(sb + SH, sb + SL);
    stacc(TH, TL);
    cvtA();            // A <- T
    // ---- Z = T*S ----
    zacc();
    product(sb + SH, sb + SL);
    stacc(ZH, ZL);
    __syncthreads();   // Z visible to both warps of this matrix

    // ---- Horner: P = C2; P = P*Z + C1; P = P*Z + C0 ----
    epi(cf.b[6], cf.b[7], cf.b[8]);    // acc = C2
    cvtA();                            // A = C2
    epi(cf.b[3], cf.b[4], cf.b[5]);    // acc = C1
    product(sb + ZH, sb + ZL);         // acc = C1 + C2*Z
    cvtA();                            // A = P
    epi(cf.b[0], cf.b[1], cf.b[2]);    // acc = C0
    product(sb + ZH, sb + ZL);         // acc = C0 + P*Z = log(X)

    // ---- store result (fp32) ----
    #pragma unroll
    for (int rb = 0; rb < 2; rb++) {
        int r0 = sr + 16 * rb + lq, r1 = r0 + 8;
        #pragma unroll
        for (int n = 0; n < 8; n++) {
            int c0 = 8 * n + 2 * lr;
            *(float2*)(out + mb + (size_t)r0 * 64 + c0) =
                make_float2(acc[rb][n][0], acc[rb][n][1]);
            *(float2*)(out + mb + (size_t)r1 * 64 + c0) =
                make_float2(acc[rb][n][2], acc[rb][n][3]);
        }
    }
}

extern "C" void kernel_launch(void* const* d_in, const int* in_sizes, int n_in,
                              void* d_out, int out_size)
{
    const float* X = (const float*)d_in[0];
    float* out = (float*)d_out;
    const int nmat = in_sizes[0] >> 12;

    // ---- Chebyshev coeffs of log on [1, 6.8] (closed form) -> monomial ----
    Coeffs cf;
    {
        const double a = 1.0, b = 6.8;
        const double m = 0.5 * (a + b);
        const double hh = 0.5 * (b - a);
        const double w = hh / m;
        const double rho = (1.0 - sqrt(1.0 - w * w)) / w;

        double c[DEG + 1];
        c[0] = log(m) - log1p(rho * rho);
        double rp = 1.0;
        for (int k = 1; k <= DEG; k++) {
            rp *= rho;
            c[k] = 2.0 * ((k & 1) ? rp : -rp) / (double)k;
        }
        double mono[DEG + 1], Tm2[DEG + 1], Tm1[DEG + 1], Tc[DEG + 1];
        for (int i = 0; i <= DEG; i++) { mono[i] = 0.0; Tm2[i] = 0.0; Tm1[i] = 0.0; }
        Tm2[0] = 1.0; mono[0] += c[0];
        Tm1[1] = 1.0; mono[1] += c[1];
        for (int k = 2; k <= DEG; k++) {
            for (int i = 0; i <= DEG; i++) Tc[i] = 0.0;
            for (int i = 0; i < k; i++) Tc[i + 1] += 2.0 * Tm1[i];
            for (int i = 0; i <= k - 2; i++) Tc[i] -= Tm2[i];
            for (int i = 0; i <= k; i++) mono[i] += c[k] * Tc[i];
            for (int i = 0; i <= DEG; i++) { Tm2[i] = Tm1[i]; Tm1[i] = Tc[i]; }
        }
        for (int i = 0; i <= DEG; i++) cf.b[i] = (float)mono[i];
        cf.mshift = (float)m;
        cf.invh = (float)(1.0 / hh);
    }

    cudaFuncSetAttribute(logmap_mma_kernel,
                         cudaFuncAttributeMaxDynamicSharedMemorySize, SMEM_TOTAL);
    logmap_mma_kernel<<<nmat / 2, 128, SMEM_TOTAL>>>(X, out, cf);
}

// round 7
// speedup vs baseline: 1.1263x; 1.1263x over previous
#include <cuda_runtime.h>
#include <cuda_bf16.h>
#include <math.h>
#include <stdint.h>

// LogMap via matrix polynomial on the tensor pipe (portable mma.sync m16n8k16 bf16).
// log(X) = p(S), S=(X-m I)/h on [1,6.8]; p = deg-8 Chebyshev fit of log.
// Paterson-Stockmeyer, Z=S^3: 4 matmuls/matrix, each = 3 bf16 MMAs (hi/lo split).
// 1 matrix per CTA, 4 warps (16-row slabs), 48KB smem -> 3-4 CTAs/SM
// (occupancy is the binding constraint per R5/R6 post-mortem).
// A operands live in registers (acc frag layout == A frag layout); P never
// round-trips through SMEM. MMAs phase-ordered (same-acc distance = 8).

#define DEG 8
struct Coeffs { float b[DEG + 1]; float mshift; float invh; };

// smem byte offsets: 6 buffers of 64 rows x 128B
#define SH 0
#define SL 8192
#define TH 16384
#define TL 24576
#define ZH 32768
#define ZL 40960
#define SMEM_TOTAL 49152

__device__ __forceinline__ uint32_t smem_u32(const void* p) {
    uint32_t a;
    asm("{ .reg .u64 t; cvta.to.shared.u64 t, %1; cvt.u32.u64 %0, t; }"
        : "=r"(a) : "l"(p));
    return a;
}

// swizzled byte offset of (row r, byte-col cb) in a 64x128B buffer
__device__ __forceinline__ uint32_t swoff(int r, int cb) {
    return (uint32_t)(r * 128 + ((((cb >> 4) ^ (r & 7))) << 4) + (cb & 15));
}

#define LDMX4(d, addr) \
    asm volatile("ldmatrix.sync.aligned.m8n8.x4.shared.b16 {%0,%1,%2,%3}, [%4];" \
        : "=r"((d)[0]), "=r"((d)[1]), "=r"((d)[2]), "=r"((d)[3]) : "r"(addr))

#define LDMX4T(d, addr) \
    asm volatile("ldmatrix.sync.aligned.m8n8.x4.trans.shared.b16 {%0,%1,%2,%3}, [%4];" \
        : "=r"((d)[0]), "=r"((d)[1]), "=r"((d)[2]), "=r"((d)[3]) : "r"(addr))

#define MMA(c, a, b0v, b1v) \
    asm volatile("mma.sync.aligned.m16n8k16.row.col.f32.bf16.bf16.f32 " \
        "{%0,%1,%2,%3}, {%4,%5,%6,%7}, {%8,%9}, {%0,%1,%2,%3};" \
        : "+f"((c)[0]), "+f"((c)[1]), "+f"((c)[2]), "+f"((c)[3]) \
        : "r"((a)[0]), "r"((a)[1]), "r"((a)[2]), "r"((a)[3]), "r"(b0v), "r"(b1v))

__device__ __forceinline__ uint32_t pk(float a, float b) {
    __nv_bfloat162 t = __floats2bfloat162_rn(a, b);
    return *reinterpret_cast<uint32_t*>(&t);
}
__device__ __forceinline__ float2 upk(uint32_t u) {
    __nv_bfloat162 t = *reinterpret_cast<__nv_bfloat162*>(&u);
    return __bfloat1622float2(t);
}
__device__ __forceinline__ float bhi(float v) {
    return __bfloat162float(__float2bfloat16_rn(v));
}

__device__ __forceinline__ void split_store8(const float* v, char* hi, char* lo) {
    float h0 = bhi(v[0]), h1 = bhi(v[1]), h2 = bhi(v[2]), h3 = bhi(v[3]);
    float h4 = bhi(v[4]), h5 = bhi(v[5]), h6 = bhi(v[6]), h7 = bhi(v[7]);
    *(uint4*)hi = make_uint4(pk(v[0], v[1]), pk(v[2], v[3]), pk(v[4], v[5]), pk(v[6], v[7]));
    *(uint4*)lo = make_uint4(pk(v[0]-h0, v[1]-h1), pk(v[2]-h2, v[3]-h3),
                             pk(v[4]-h4, v[5]-h5), pk(v[6]-h6, v[7]-h7));
}

__global__ void __launch_bounds__(128, 3)
logmap_mma_kernel(const float* __restrict__ X, float* __restrict__ out, Coeffs cf)
{
    extern __shared__ char sm[];
    const uint32_t sb = smem_u32(sm);
    const int tid = threadIdx.x;
    const int w = tid >> 5;              // warp owns rows [16w, 16w+16)
    const int l = tid & 31;
    const int sr = 16 * w;
    const int lq = l >> 2, lr = l & 3;
    const int lmr = l & 15;
    const int lmc16 = (l >> 4) & 1;
    const int key = lmr & 7;
    const size_t mb = (size_t)blockIdx.x * 4096;

    // hoisted offset tables (thread-constant)
    uint32_t colx[4], kb[4];
    #pragma unroll
    for (int j = 0; j < 4; j++) colx[j] = (uint32_t)((((2*j + lmc16) ^ key)) << 4);
    #pragma unroll
    for (int kk = 0; kk < 4; kk++) kb[kk] = (uint32_t)((16*kk + lmr) * 128);
    const uint32_t arow = (uint32_t)((sr + lmr) * 128);

    // ---- load X (half-row per thread), S = (X - m I)/h, write S hi/lo ----
    {
        const int row = sr + (l >> 1);
        const int c0 = 32 * (l & 1);
        const float4* xr = (const float4*)(X + mb + (size_t)row * 64 + c0);
        float v[32];
        #pragma unroll
        for (int q = 0; q < 8; q++) {
            float4 f = xr[q];
            v[4*q] = f.x; v[4*q+1] = f.y; v[4*q+2] = f.z; v[4*q+3] = f.w;
        }
        #pragma unroll
        for (int i = 0; i < 32; i++) {
            float t = v[i];
            if (c0 + i == row) t -= cf.mshift;
            v[i] = t * cf.invh;
        }
        #pragma unroll
        for (int q = 0; q < 4; q++) {
            uint32_t o = swoff(row, 2 * c0 + 16 * q);
            split_store8(v + 8 * q, sm + SH + o, sm + SL + o);
        }
    }
    __syncthreads();

    float acc[8][4];
    uint32_t ah[4][4], al[4][4];

    auto zacc = [&] {
        #pragma unroll
        for (int n = 0; n < 8; n++)
            #pragma unroll
            for (int q = 0; q < 4; q++) acc[n][q] = 0.f;
    };

    auto ldaS = [&] {
        #pragma unroll
        for (int kk = 0; kk < 4; kk++) {
            uint32_t o = arow + colx[kk];
            LDMX4(ah[kk], sb + SH + o);
            LDMX4(al[kk], sb + SL + o);
        }
    };

    // A frags <- acc (hi/lo bf16 split)
    auto cvtA = [&] {
        #pragma unroll
        for (int kk = 0; kk < 4; kk++) {
            float c00 = acc[2*kk][0],   c01 = acc[2*kk][1];
            float c02 = acc[2*kk][2],   c03 = acc[2*kk][3];
            float d00 = acc[2*kk+1][0], d01 = acc[2*kk+1][1];
            float d02 = acc[2*kk+1][2], d03 = acc[2*kk+1][3];
            ah[kk][0] = pk(c00, c01); ah[kk][1] = pk(c02, c03);
            ah[kk][2] = pk(d00, d01); ah[kk][3] = pk(d02, d03);
            al[kk][0] = pk(c00 - bhi(c00), c01 - bhi(c01));
            al[kk][1] = pk(c02 - bhi(c02), c03 - bhi(c03));
            al[kk][2] = pk(d00 - bhi(d00), d01 - bhi(d01));
            al[kk][3] = pk(d02 - bhi(d02), d03 - bhi(d03));
        }
    };

    // acc += A(frags) * B(smem hi/lo); phases of 8 distinct accumulators
    auto product = [&](uint32_t bhBase, uint32_t blBase) {
        #pragma unroll
        for (int kk = 0; kk < 4; kk++) {
            uint32_t b0[4], b1[4], b2[4], b3[4];
            LDMX4T(b0, bhBase + kb[kk] + colx[0]);
            LDMX4T(b1, bhBase + kb[kk] + colx[1]);
            LDMX4T(b2, bhBase + kb[kk] + colx[2]);
            LDMX4T(b3, bhBase + kb[kk] + colx[3]);
            // phase 1: ah x bh (8 distinct accs)
            MMA(acc[0], ah[kk], b0[0], b0[1]);
            MMA(acc[1], ah[kk], b0[2], b0[3]);
            MMA(acc[2], ah[kk], b1[0], b1[1]);
            MMA(acc[3], ah[kk], b1[2], b1[3]);
            MMA(acc[4], ah[kk], b2[0], b2[1]);
            MMA(acc[5], ah[kk], b2[2], b2[3]);
            MMA(acc[6], ah[kk], b3[0], b3[1]);
            MMA(acc[7], ah[kk], b3[2], b3[3]);
            // phase 2: al x bh
            MMA(acc[0], al[kk], b0[0], b0[1]);
            MMA(acc[1], al[kk], b0[2], b0[3]);
            MMA(acc[2], al[kk], b1[0], b1[1]);
            MMA(acc[3], al[kk], b1[2], b1[3]);
            MMA(acc[4], al[kk], b2[0], b2[1]);
            MMA(acc[5], al[kk], b2[2], b2[3]);
            MMA(acc[6], al[kk], b3[0], b3[1]);
            MMA(acc[7], al[kk], b3[2], b3[3]);
            // phase 3: ah x bl
            uint32_t c0[4], c1[4], c2[4], c3[4];
            LDMX4T(c0, blBase + kb[kk] + colx[0]);
            LDMX4T(c1, blBase + kb[kk] + colx[1]);
            LDMX4T(c2, blBase + kb[kk] + colx[2]);
            LDMX4T(c3, blBase + kb[kk] + colx[3]);
            MMA(acc[0], ah[kk], c0[0], c0[1]);
            MMA(acc[1], ah[kk], c0[2], c0[3]);
            MMA(acc[2], ah[kk], c1[0], c1[1]);
            MMA(acc[3], ah[kk], c1[2], c1[3]);
            MMA(acc[4], ah[kk], c2[0], c2[1]);
            MMA(acc[5], ah[kk], c2[2], c2[3]);
            MMA(acc[6], ah[kk], c3[0], c3[1]);
            MMA(acc[7], ah[kk], c3[2], c3[3]);
        }
    };

    auto stacc = [&](int hB, int lB) {
        int r0 = sr + lq, r1 = r0 + 8;
        #pragma unroll
        for (int n = 0; n < 8; n++) {
            int cb = 16 * n + 4 * lr;
            float a0 = acc[n][0], a1 = acc[n][1];
            float a2 = acc[n][2], a3 = acc[n][3];
            *(uint32_t*)(sm + hB + swoff(r0, cb)) = pk(a0, a1);
            *(uint32_t*)(sm + hB + swoff(r1, cb)) = pk(a2, a3);
            *(uint32_t*)(sm + lB + swoff(r0, cb)) = pk(a0 - bhi(a0), a1 - bhi(a1));
            *(uint32_t*)(sm + lB + swoff(r1, cb)) = pk(a2 - bhi(a2), a3 - bhi(a3));
        }
    };

    // acc = b0*I + b1*S + b2*T (overwrites acc)
    auto epi = [&](float b0, float b1, float b2) {
        #pragma unroll
        for (int g = 0; g < 4; g++) {
            uint32_t shf[4], slf[4], thf[4], tlf[4];
            uint32_t o = arow + colx[g];
            LDMX4(shf, sb + SH + o);
            LDMX4(slf, sb + SL + o);
            LDMX4(thf, sb + TH + o);
            LDMX4(tlf, sb + TL + o);
            #pragma unroll
            for (int q = 0; q < 4; q++) {
                float2 s = upk(shf[q]), s2 = upk(slf[q]);
                float2 t = upk(thf[q]), t2 = upk(tlf[q]);
                float sx = s.x + s2.x, sy = s.y + s2.y;
                float tx = t.x + t2.x, ty = t.y + t2.y;
                int n = 2 * g + (q >> 1), c = (q & 1) * 2;
                acc[n][c]     = b1 * sx + b2 * tx;
                acc[n][c + 1] = b1 * sy + b2 * ty;
            }
        }
        int r0 = sr + lq, r1 = r0 + 8;
        #pragma unroll
        for (int n = 0; n < 8; n++) {
            int c0 = 8 * n + 2 * lr;
            if (c0 == r0)     acc[n][0] += b0;
            if (c0 + 1 == r0) acc[n][1] += b0;
            if (c0 == r1)     acc[n][2] += b0;
            if (c0 + 1 == r1) acc[n][3] += b0;
        }
    };

    // ---- T = S*S ----
    ldaS();
    zacc();
    product(sb + SH, sb + SL);
    stacc(TH, TL);
    cvtA();            // A <- T
    // ---- Z = T*S ----
    zacc();
    product(sb + SH, sb + SL);
    stacc(ZH, ZL);
    __syncthreads();   // T, Z visible to all warps

    // ---- Horner: P = C2; P = P*Z + C1; P = P*Z + C0 ----
    epi(cf.b[6], cf.b[7], cf.b[8]);    // acc = C2
    cvtA();                            // A = C2
    epi(cf.b[3], cf.b[4], cf.b[5]);    // acc = C1
    product(sb + ZH, sb + ZL);         // acc = C1 + C2*Z
    cvtA();                            // A = P
    epi(cf.b[0], cf.b[1], cf.b[2]);    // acc = C0
    product(sb + ZH, sb + ZL);         // acc = C0 + P*Z = log(X)

    // ---- store result (fp32) ----
    {
        int r0 = sr + lq, r1 = r0 + 8;
        #pragma unroll
        for (int n = 0; n < 8; n++) {
            int c0 = 8 * n + 2 * lr;
            *(float2*)(out + mb + (size_t)r0 * 64 + c0) =
                make_float2(acc[n][0], acc[n][1]);
            *(float2*)(out + mb + (size_t)r1 * 64 + c0) =
                make_float2(acc[n][2], acc[n][3]);
        }
    }
}

extern "C" void kernel_launch(void* const* d_in, const int* in_sizes, int n_in,
                              void* d_out, int out_size)
{
    const float* X = (const float*)d_in[0];
    float* out = (float*)d_out;
    const int nmat = in_sizes[0] >> 12;

    // ---- Chebyshev coeffs of log on [1, 6.8] (closed form) -> monomial ----
    Coeffs cf;
    {
        const double a = 1.0, b = 6.8;
        const double m = 0.5 * (a + b);
        const double hh = 0.5 * (b - a);
        const double w = hh / m;
        const double rho = (1.0 - sqrt(1.0 - w * w)) / w;

        double c[DEG + 1];
        c[0] = log(m) - log1p(rho * rho);
        double rp = 1.0;
        for (int k = 1; k <= DEG; k++) {
            rp *= rho;
            c[k] = 2.0 * ((k & 1) ? rp : -rp) / (double)k;
        }
        double mono[DEG + 1], Tm2[DEG + 1], Tm1[DEG + 1], Tc[DEG + 1];
        for (int i = 0; i <= DEG; i++) { mono[i] = 0.0; Tm2[i] = 0.0; Tm1[i] = 0.0; }
        Tm2[0] = 1.0; mono[0] += c[0];
        Tm1[1] = 1.0; mono[1] += c[1];
        for (int k = 2; k <= DEG; k++) {
            for (int i = 0; i <= DEG; i++) Tc[i] = 0.0;
            for (int i = 0; i < k; i++) Tc[i + 1] += 2.0 * Tm1[i];
            for (int i = 0; i <= k - 2; i++) Tc[i] -= Tm2[i];
            for (int i = 0; i <= k; i++) mono[i] += c[k] * Tc[i];
            for (int i = 0; i <= DEG; i++) { Tm2[i] = Tm1[i]; Tm1[i] = Tc[i]; }
        }
        for (int i = 0; i <= DEG; i++) cf.b[i] = (float)mono[i];
        cf.mshift = (float)m;
        cf.invh = (float)(1.0 / hh);
    }

    cudaFuncSetAttribute(logmap_mma_kernel,
                         cudaFuncAttributeMaxDynamicSharedMemorySize, SMEM_TOTAL);
    logmap_mma_kernel<<<nmat, 128, SMEM_TOTAL>>>(X, out, cf);
}

// round 8
// speedup vs baseline: 1.1729x; 1.0413x over previous
#include <cuda_runtime.h>
#include <cuda_bf16.h>
#include <math.h>
#include <stdint.h>

// LogMap via matrix polynomial on the tensor pipe (portable mma.sync m16n8k16 bf16).
// log(X) = p(S), S=(X-m I)/h on [1,6.8]; p = deg-8 Chebyshev fit of log.
// Paterson-Stockmeyer, Z=S^3: 4 matmuls/matrix, each = 3 bf16 MMAs (hi/lo split).
// 1 matrix per CTA, 4 warps (16-row slabs). launch_bounds(128,4) caps regs at
// 128 -> 4 CTAs/SM (16 warps): occupancy is the binding constraint (R5-R7).
// B-fragment live set halved (2 col-groups at a time) to fit the reg budget.

#define DEG 8
struct Coeffs { float b[DEG + 1]; float mshift; float invh; };

// smem byte offsets: 6 buffers of 64 rows x 128B
#define SH 0
#define SL 8192
#define TH 16384
#define TL 24576
#define ZH 32768
#define ZL 40960
#define SMEM_TOTAL 49152

__device__ __forceinline__ uint32_t smem_u32(const void* p) {
    uint32_t a;
    asm("{ .reg .u64 t; cvta.to.shared.u64 t, %1; cvt.u32.u64 %0, t; }"
        : "=r"(a) : "l"(p));
    return a;
}

// swizzled byte offset of (row r, byte-col cb) in a 64x128B buffer
__device__ __forceinline__ uint32_t swoff(int r, int cb) {
    return (uint32_t)(r * 128 + ((((cb >> 4) ^ (r & 7))) << 4) + (cb & 15));
}

#define LDMX4(d, addr) \
    asm volatile("ldmatrix.sync.aligned.m8n8.x4.shared.b16 {%0,%1,%2,%3}, [%4];" \
        : "=r"((d)[0]), "=r"((d)[1]), "=r"((d)[2]), "=r"((d)[3]) : "r"(addr))

#define LDMX4T(d, addr) \
    asm volatile("ldmatrix.sync.aligned.m8n8.x4.trans.shared.b16 {%0,%1,%2,%3}, [%4];" \
        : "=r"((d)[0]), "=r"((d)[1]), "=r"((d)[2]), "=r"((d)[3]) : "r"(addr))

#define MMA(c, a, b0v, b1v) \
    asm volatile("mma.sync.aligned.m16n8k16.row.col.f32.bf16.bf16.f32 " \
        "{%0,%1,%2,%3}, {%4,%5,%6,%7}, {%8,%9}, {%0,%1,%2,%3};" \
        : "+f"((c)[0]), "+f"((c)[1]), "+f"((c)[2]), "+f"((c)[3]) \
        : "r"((a)[0]), "r"((a)[1]), "r"((a)[2]), "r"((a)[3]), "r"(b0v), "r"(b1v))

__device__ __forceinline__ uint32_t pk(float a, float b) {
    __nv_bfloat162 t = __floats2bfloat162_rn(a, b);
    return *reinterpret_cast<uint32_t*>(&t);
}
__device__ __forceinline__ float2 upk(uint32_t u) {
    __nv_bfloat162 t = *reinterpret_cast<__nv_bfloat162*>(&u);
    return __bfloat1622float2(t);
}
__device__ __forceinline__ float bhi(float v) {
    return __bfloat162float(__float2bfloat16_rn(v));
}

__device__ __forceinline__ void split_store8(const float* v, char* hi, char* lo) {
    float h0 = bhi(v[0]), h1 = bhi(v[1]), h2 = bhi(v[2]), h3 = bhi(v[3]);
    float h4 = bhi(v[4]), h5 = bhi(v[5]), h6 = bhi(v[6]), h7 = bhi(v[7]);
    *(uint4*)hi = make_uint4(pk(v[0], v[1]), pk(v[2], v[3]), pk(v[4], v[5]), pk(v[6], v[7]));
    *(uint4*)lo = make_uint4(pk(v[0]-h0, v[1]-h1), pk(v[2]-h2, v[3]-h3),
                             pk(v[4]-h4, v[5]-h5), pk(v[6]-h6, v[7]-h7));
}

__global__ void __launch_bounds__(128, 4)
logmap_mma_kernel(const float* __restrict__ X, float* __restrict__ out, Coeffs cf)
{
    extern __shared__ char sm[];
    const uint32_t sb = smem_u32(sm);
    const int tid = threadIdx.x;
    const int w = tid >> 5;              // warp owns rows [16w, 16w+16)
    const int l = tid & 31;
    const int sr = 16 * w;
    const int lq = l >> 2, lr = l & 3;
    const int lmr = l & 15;
    const int lmc16 = (l >> 4) & 1;
    const int key = lmr & 7;
    const size_t mb = (size_t)blockIdx.x * 4096;

    // hoisted offset tables (thread-constant)
    uint32_t colx[4];
    #pragma unroll
    for (int j = 0; j < 4; j++) colx[j] = (uint32_t)((((2*j + lmc16) ^ key)) << 4);
    const uint32_t arow = (uint32_t)((sr + lmr) * 128);
    const int er0 = sr + lq, er1 = er0 + 8;      // stacc/epi rows

    // ---- load X (half-row per thread), S = (X - m I)/h, write S hi/lo ----
    {
        const int row = sr + (l >> 1);
        const int c0 = 32 * (l & 1);
        const float4* xr = (const float4*)(X + mb + (size_t)row * 64 + c0);
        float v[32];
        #pragma unroll
        for (int q = 0; q < 8; q++) {
            float4 f = xr[q];
            v[4*q] = f.x; v[4*q+1] = f.y; v[4*q+2] = f.z; v[4*q+3] = f.w;
        }
        #pragma unroll
        for (int i = 0; i < 32; i++) {
            float t = v[i];
            if (c0 + i == row) t -= cf.mshift;
            v[i] = t * cf.invh;
        }
        #pragma unroll
        for (int q = 0; q < 4; q++) {
            uint32_t o = swoff(row, 2 * c0 + 16 * q);
            split_store8(v + 8 * q, sm + SH + o, sm + SL + o);
        }
    }
    __syncthreads();

    float acc[8][4];
    uint32_t ah[4][4], al[4][4];

    auto zacc = [&] {
        #pragma unroll
        for (int n = 0; n < 8; n++)
            #pragma unroll
            for (int q = 0; q < 4; q++) acc[n][q] = 0.f;
    };

    auto ldaS = [&] {
        #pragma unroll
        for (int kk = 0; kk < 4; kk++) {
            uint32_t o = arow + colx[kk];
            LDMX4(ah[kk], sb + SH + o);
            LDMX4(al[kk], sb + SL + o);
        }
    };

    // A frags <- acc (hi/lo bf16 split)
    auto cvtA = [&] {
        #pragma unroll
        for (int kk = 0; kk < 4; kk++) {
            float c00 = acc[2*kk][0],   c01 = acc[2*kk][1];
            float c02 = acc[2*kk][2],   c03 = acc[2*kk][3];
            float d00 = acc[2*kk+1][0], d01 = acc[2*kk+1][1];
            float d02 = acc[2*kk+1][2], d03 = acc[2*kk+1][3];
            ah[kk][0] = pk(c00, c01); ah[kk][1] = pk(c02, c03);
            ah[kk][2] = pk(d00, d01); ah[kk][3] = pk(d02, d03);
            al[kk][0] = pk(c00 - bhi(c00), c01 - bhi(c01));
            al[kk][1] = pk(c02 - bhi(c02), c03 - bhi(c03));
            al[kk][2] = pk(d00 - bhi(d00), d01 - bhi(d01));
            al[kk][3] = pk(d02 - bhi(d02), d03 - bhi(d03));
        }
    };

    // acc += A(frags)*B(smem hi/lo); 2 col-groups live (16 B-regs), 4-acc phases
    auto product = [&](uint32_t bhBase, uint32_t blBase) {
        #pragma unroll
        for (int kk = 0; kk < 4; kk++) {
            const uint32_t kbo = (uint32_t)((16*kk + lmr) * 128);
            #pragma unroll
            for (int jp = 0; jp < 2; jp++) {
                uint32_t o0 = kbo + colx[2*jp], o1 = kbo + colx[2*jp + 1];
                uint32_t b0[4], b1[4];
                LDMX4T(b0, bhBase + o0);
                LDMX4T(b1, bhBase + o1);
                MMA(acc[4*jp+0], ah[kk], b0[0], b0[1]);
                MMA(acc[4*jp+1], ah[kk], b0[2], b0[3]);
                MMA(acc[4*jp+2], ah[kk], b1[0], b1[1]);
                MMA(acc[4*jp+3], ah[kk], b1[2], b1[3]);
                MMA(acc[4*jp+0], al[kk], b0[0], b0[1]);
                MMA(acc[4*jp+1], al[kk], b0[2], b0[3]);
                MMA(acc[4*jp+2], al[kk], b1[0], b1[1]);
                MMA(acc[4*jp+3], al[kk], b1[2], b1[3]);
                LDMX4T(b0, blBase + o0);
                LDMX4T(b1, blBase + o1);
                MMA(acc[4*jp+0], ah[kk], b0[0], b0[1]);
                MMA(acc[4*jp+1], ah[kk], b0[2], b0[3]);
                MMA(acc[4*jp+2], ah[kk], b1[0], b1[1]);
                MMA(acc[4*jp+3], ah[kk], b1[2], b1[3]);
            }
        }
    };

    auto stacc = [&](int hB, int lB) {
        #pragma unroll
        for (int n = 0; n < 8; n++) {
            int cb = 16 * n + 4 * lr;
            float a0 = acc[n][0], a1 = acc[n][1];
            float a2 = acc[n][2], a3 = acc[n][3];
            *(uint32_t*)(sm + hB + swoff(er0, cb)) = pk(a0, a1);
            *(uint32_t*)(sm + hB + swoff(er1, cb)) = pk(a2, a3);
            *(uint32_t*)(sm + lB + swoff(er0, cb)) = pk(a0 - bhi(a0), a1 - bhi(a1));
            *(uint32_t*)(sm + lB + swoff(er1, cb)) = pk(a2 - bhi(a2), a3 - bhi(a3));
        }
    };

    // acc = b0*I + b1*S + b2*T (overwrites acc)
    auto epi = [&](float b0, float b1, float b2) {
        #pragma unroll
        for (int g = 0; g < 4; g++) {
            uint32_t shf[4], slf[4], thf[4], tlf[4];
            uint32_t o = arow + colx[g];
            LDMX4(shf, sb + SH + o);
            LDMX4(slf, sb + SL + o);
            LDMX4(thf, sb + TH + o);
            LDMX4(tlf, sb + TL + o);
            #pragma unroll
            for (int q = 0; q < 4; q++) {
                float2 s = upk(shf[q]), s2 = upk(slf[q]);
                float2 t = upk(thf[q]), t2 = upk(tlf[q]);
                float sx = s.x + s2.x, sy = s.y + s2.y;
                float tx = t.x + t2.x, ty = t.y + t2.y;
                int n = 2 * g + (q >> 1), c = (q & 1) * 2;
                acc[n][c]     = b1 * sx + b2 * tx;
                acc[n][c + 1] = b1 * sy + b2 * ty;
            }
        }
        #pragma unroll
        for (int n = 0; n < 8; n++) {
            int c0 = 8 * n + 2 * lr;
            if (c0 == er0)     acc[n][0] += b0;
            if (c0 + 1 == er0) acc[n][1] += b0;
            if (c0 == er1)     acc[n][2] += b0;
            if (c0 + 1 == er1) acc[n][3] += b0;
        }
    };

    // ---- T = S*S ----
    ldaS();
    zacc();
    product(sb + SH, sb + SL);
    stacc(TH, TL);
    cvtA();            // A <- T
    // ---- Z = T*S ----
    zacc();
    product(sb + SH, sb + SL);
    stacc(ZH, ZL);
    __syncthreads();   // T, Z visible to all warps

    // ---- Horner: P = C2; P = P*Z + C1; P = P*Z + C0 ----
    epi(cf.b[6], cf.b[7], cf.b[8]);    // acc = C2
    cvtA();                            // A = C2
    epi(cf.b[3], cf.b[4], cf.b[5]);    // acc = C1
    product(sb + ZH, sb + ZL);         // acc = C1 + C2*Z
    cvtA();                            // A = P
    epi(cf.b[0], cf.b[1], cf.b[2]);    // acc = C0
    product(sb + ZH, sb + ZL);         // acc = C0 + P*Z = log(X)

    // ---- store result (fp32) ----
    #pragma unroll
    for (int n = 0; n < 8; n++) {
        int c0 = 8 * n + 2 * lr;
        *(float2*)(out + mb + (size_t)er0 * 64 + c0) =
            make_float2(acc[n][0], acc[n][1]);
        *(float2*)(out + mb + (size_t)er1 * 64 + c0) =
            make_float2(acc[n][2], acc[n][3]);
    }
}

extern "C" void kernel_launch(void* const* d_in, const int* in_sizes, int n_in,
                              void* d_out, int out_size)
{
    const float* X = (const float*)d_in[0];
    float* out = (float*)d_out;
    const int nmat = in_sizes[0] >> 12;

    // ---- Chebyshev coeffs of log on [1, 6.8] (closed form) -> monomial ----
    Coeffs cf;
    {
        const double a = 1.0, b = 6.8;
        const double m = 0.5 * (a + b);
        const double hh = 0.5 * (b - a);
        const double w = hh / m;
        const double rho = (1.0 - sqrt(1.0 - w * w)) / w;

        double c[DEG + 1];
        c[0] = log(m) - log1p(rho * rho);
        double rp = 1.0;
        for (int k = 1; k <= DEG; k++) {
            rp *= rho;
            c[k] = 2.0 * ((k & 1) ? rp : -rp) / (double)k;
        }
        double mono[DEG + 1], Tm2[DEG + 1], Tm1[DEG + 1], Tc[DEG + 1];
        for (int i = 0; i <= DEG; i++) { mono[i] = 0.0; Tm2[i] = 0.0; Tm1[i] = 0.0; }
        Tm2[0] = 1.0; mono[0] += c[0];
        Tm1[1] = 1.0; mono[1] += c[1];
        for (int k = 2; k <= DEG; k++) {
            for (int i = 0; i <= DEG; i++) Tc[i] = 0.0;
            for (int i = 0; i < k; i++) Tc[i + 1] += 2.0 * Tm1[i];
            for (int i = 0; i <= k - 2; i++) Tc[i] -= Tm2[i];
            for (int i = 0; i <= k; i++) mono[i] += c[k] * Tc[i];
            for (int i = 0; i <= DEG; i++) { Tm2[i] = Tm1[i]; Tm1[i] = Tc[i]; }
        }
        for (int i = 0; i <= DEG; i++) cf.b[i] = (float)mono[i];
        cf.mshift = (float)m;
        cf.invh = (float)(1.0 / hh);
    }

    cudaFuncSetAttribute(logmap_mma_kernel,
                         cudaFuncAttributeMaxDynamicSharedMemorySize, SMEM_TOTAL);
    logmap_mma_kernel<<<nmat, 128, SMEM_TOTAL>>>(X, out, cf);
}